// round 7
// baseline (speedup 1.0000x reference)
#include <cuda_runtime.h>

// ADC module: out = x + alpha_c * sum_{3x3, zero-pad} |x - neighbor|
// x: (8, 64, 256, 256) fp32, alpha: (64,) fp32
//
// R5: software-pipelined rolling window. One warp per 32-row strip.
// 4 finished rows resident (r-1..r+2); each iteration issues raw loads for
// rows r+3,r+4 (4 LDG.128 = 2KB in flight per warp), computes rows r,r+1
// from resident rows, then does the halo SHFLs for the new rows after the
// stores. Load->use distance = 1 full iteration -> latency hidden.

#define IMG_H 256
#define IMG_W 256
#define STRIP_ROWS 32
#define N_IMG (8 * 64)
#define STRIPS_PER_IMG (IMG_H / STRIP_ROWS)   // 8
#define TOTAL_WARPS (N_IMG * STRIPS_PER_IMG)  // 4096
#define BLOCK_THREADS 256
#define GRID_BLOCKS (TOTAL_WARPS * 32 / BLOCK_THREADS)  // 512

struct Row {
    float v[8];
    float lh;   // value at col (lane*8 - 1), 0 at image edge
    float rh;   // value at col (lane*8 + 8), 0 at image edge
};

// Issue the vector loads only; no dependent ops (keeps the LDG in flight).
__device__ __forceinline__ void load_raw(Row& row, const float* __restrict__ img,
                                         int r, int rlo, int rhi, int lane) {
    if (r >= rlo && r <= rhi) {
        const float4* p = reinterpret_cast<const float4*>(img + (size_t)r * IMG_W + lane * 8);
        float4 a = __ldcs(p);
        float4 b = __ldcs(p + 1);
        row.v[0] = a.x; row.v[1] = a.y; row.v[2] = a.z; row.v[3] = a.w;
        row.v[4] = b.x; row.v[5] = b.y; row.v[6] = b.z; row.v[7] = b.w;
    } else {
#pragma unroll
        for (int i = 0; i < 8; i++) row.v[i] = 0.0f;
    }
}

// Halo exchange (consumes the loaded values) — done well after the LDGs.
__device__ __forceinline__ void finish_row(Row& row, int lane) {
    float left  = __shfl_up_sync(0xffffffffu, row.v[7], 1);
    float right = __shfl_down_sync(0xffffffffu, row.v[0], 1);
    row.lh = (lane == 0)  ? 0.0f : left;
    row.rh = (lane == 31) ? 0.0f : right;
}

__device__ __forceinline__ void compute_store(const Row& p, const Row& c, const Row& n,
                                              float a, float* __restrict__ oi,
                                              int r, int lane) {
    float o[8];
#pragma unroll
    for (int j = 0; j < 8; ++j) {
        float cc = c.v[j];
        float l  = (j == 0) ? c.lh : c.v[j - 1];
        float rr = (j == 7) ? c.rh : c.v[j + 1];
        float pl = (j == 0) ? p.lh : p.v[j - 1];
        float pc = p.v[j];
        float pr = (j == 7) ? p.rh : p.v[j + 1];
        float nl = (j == 0) ? n.lh : n.v[j - 1];
        float nc = n.v[j];
        float nr = (j == 7) ? n.rh : n.v[j + 1];

        float s = fabsf(cc - pl) + fabsf(cc - pc) + fabsf(cc - pr)
                + fabsf(cc - l)                   + fabsf(cc - rr)
                + fabsf(cc - nl) + fabsf(cc - nc) + fabsf(cc - nr);
        o[j] = fmaf(a, s, cc);
    }
    float4* po = reinterpret_cast<float4*>(oi + (size_t)r * IMG_W + lane * 8);
    __stcs(po,     make_float4(o[0], o[1], o[2], o[3]));
    __stcs(po + 1, make_float4(o[4], o[5], o[6], o[7]));
}

__global__ void __launch_bounds__(BLOCK_THREADS)
adc_kernel(const float* __restrict__ x, const float* __restrict__ alpha,
           float* __restrict__ out) {
    int gwarp = (blockIdx.x * BLOCK_THREADS + threadIdx.x) >> 5;
    int lane  = threadIdx.x & 31;

    int img   = gwarp / STRIPS_PER_IMG;
    int strip = gwarp - img * STRIPS_PER_IMG;
    int ch    = img & 63;
    float a   = __ldg(&alpha[ch]);

    const float* xi = x   + (size_t)img * IMG_H * IMG_W;
    float*       oi = out + (size_t)img * IMG_H * IMG_W;

    int r0  = strip * STRIP_ROWS;
    // Valid load window: rows [r0-1, r0+STRIP_ROWS] clipped to image.
    int rlo = (r0 - 1 < 0) ? 0 : r0 - 1;
    int rhi = (r0 + STRIP_ROWS > IMG_H - 1) ? IMG_H - 1 : r0 + STRIP_ROWS;

    Row ra, rb, rc, rd;                       // rows r-1, r, r+1, r+2 (finished)
    load_raw(ra, xi, r0 - 1, rlo, rhi, lane);
    load_raw(rb, xi, r0,     rlo, rhi, lane);
    load_raw(rc, xi, r0 + 1, rlo, rhi, lane);
    load_raw(rd, xi, r0 + 2, rlo, rhi, lane);
    finish_row(ra, lane); finish_row(rb, lane);
    finish_row(rc, lane); finish_row(rd, lane);

#pragma unroll 2
    for (int r = r0; r < r0 + STRIP_ROWS; r += 2) {
        Row re, rf;                           // rows r+3, r+4 — issue loads now
        load_raw(re, xi, r + 3, rlo, rhi, lane);
        load_raw(rf, xi, r + 4, rlo, rhi, lane);

        // Compute from resident rows only — no dependency on re/rf.
        compute_store(ra, rb, rc, a, oi, r,     lane);
        compute_store(rb, rc, rd, a, oi, r + 1, lane);

        // Now consume the new loads (latency covered by the compute above).
        finish_row(re, lane);
        finish_row(rf, lane);

        ra = rc; rb = rd; rc = re; rd = rf;
    }
}

extern "C" void kernel_launch(void* const* d_in, const int* in_sizes, int n_in,
                              void* d_out, int out_size) {
    const float* x     = (const float*)d_in[0];
    const float* alpha = (const float*)d_in[1];
    float*       out   = (float*)d_out;
    adc_kernel<<<GRID_BLOCKS, BLOCK_THREADS>>>(x, alpha, out);
}